// round 6
// baseline (speedup 1.0000x reference)
#include <cuda_runtime.h>
#include <cstdint>

// DenseRoutingMaskLayer: per-row argmax over 8 routing logits selects a
// contiguous 512-float chunk of the 4096-wide input row.
//   inputs:          [B=16384, D=4096] f32   (d_in[0])
//   routing_inputs:  [B=16384, R=8]    f32   (d_in[1])
//   out:             [B=16384, W=512]  f32
//
// Round 5 retry (previous attempt died to a container infra failure).
// HALF-row per warp -> minimal registers, maximal warp count.
//  - 2 warps cooperate on one row; each lane moves 2 float4 (1KB/warp).
//  - each half-warp independently computes the row argmax from the 8
//    logits (lanes 0-7 load; 3x shfl_xor max + ballot + ffs; ffs picks
//    the lowest index == jnp.argmax first-occurrence tie-break).
//  - all indexing in 32-bit (16384*4096 < 2^31).
//  - target: ~20 regs, occupancy ~90-100%, 32768 concurrent warps.

constexpr int WARPS_PER_CTA = 8;
constexpr int ROWS_PER_CTA  = WARPS_PER_CTA / 2;   // 4

__global__ __launch_bounds__(256)
void dense_routing_mask_kernel(const float* __restrict__ inputs,
                               const float* __restrict__ routing,
                               float* __restrict__ out) {
    const int warp = threadIdx.x >> 5;
    const int lane = threadIdx.x & 31;
    const int row  = blockIdx.x * ROWS_PER_CTA + (warp >> 1);
    const int half = warp & 1;

    // ---- argmax over this row's 8 logits (lanes 0-7 active) ----
    const float NEG_INF = -__int_as_float(0x7f800000);
    float v = (lane < 8) ? routing[row * 8 + lane] : NEG_INF;

    float m = v;
    #pragma unroll
    for (int off = 1; off < 8; off <<= 1)
        m = fmaxf(m, __shfl_xor_sync(0xffffffffu, m, off));

    const unsigned b = __ballot_sync(0xffffffffu, v == m);
    const int idx = __ffs(b & 0xFFu) - 1;   // first occurrence wins

    // ---- copy half a chunk: 64 float4, 2 per lane ----
    // row stride: 1024 float4; chunk: 128 float4; half: 64 float4
    const float4* __restrict__ src = reinterpret_cast<const float4*>(inputs)
        + row * 1024 + idx * 128 + half * 64;
    float4* __restrict__ dst = reinterpret_cast<float4*>(out)
        + row * 128 + half * 64;

    float4 a0 = src[lane];
    float4 a1 = src[lane + 32];
    dst[lane]      = a0;
    dst[lane + 32] = a1;
}

extern "C" void kernel_launch(void* const* d_in, const int* in_sizes, int n_in,
                              void* d_out, int out_size) {
    const float* inputs  = (const float*)d_in[0];
    const float* routing = (const float*)d_in[1];
    float* out = (float*)d_out;

    const int B = in_sizes[1] / 8;                 // 16384
    const int blocks = B / ROWS_PER_CTA;           // 4096

    dense_routing_mask_kernel<<<blocks, 256>>>(inputs, routing, out);
}

// round 7
// speedup vs baseline: 1.1532x; 1.1532x over previous
#include <cuda_runtime.h>
#include <cstdint>

// DenseRoutingMaskLayer: per-row argmax over 8 routing logits selects a
// contiguous 512-float chunk of the 4096-wide input row.
//   inputs:          [B=16384, D=4096] f32   (d_in[0])
//   routing_inputs:  [B=16384, R=8]    f32   (d_in[1])
//   out:             [B=16384, W=512]  f32
//
// Round 7: R1 structure (1 row/warp, best so far) with the per-row prologue
// collapsed:
//  - routing logits via TWO uniform float4 broadcast loads (__ldg) -- every
//    lane holds all 8 values; no shuffles, no ballot.
//  - branchless depth-3 comparison tree; strict '>' keeps the lower index,
//    matching jnp.argmax first-occurrence tie-break.
//  - chunk copy: 4x __ldcg (L2-only, single-touch data) batched before
//    4 stores.

struct VI { float v; int i; };

__device__ __forceinline__ VI vmax(VI a, VI b) {
    // b has the higher index; keep a on ties -> first occurrence wins
    VI r;
    r.v = (b.v > a.v) ? b.v : a.v;
    r.i = (b.v > a.v) ? b.i : a.i;
    return r;
}

__global__ __launch_bounds__(256, 8)
void dense_routing_mask_kernel(const float* __restrict__ inputs,
                               const float* __restrict__ routing,
                               float* __restrict__ out) {
    const int warp = threadIdx.x >> 5;
    const int lane = threadIdx.x & 31;
    const int row  = blockIdx.x * 8 + warp;

    // ---- argmax: all lanes load the same 8 logits (broadcast) ----
    const float4* r4 = reinterpret_cast<const float4*>(routing) + row * 2;
    const float4 a = __ldg(r4);
    const float4 b = __ldg(r4 + 1);

    VI m01 = vmax(VI{a.x, 0}, VI{a.y, 1});
    VI m23 = vmax(VI{a.z, 2}, VI{a.w, 3});
    VI m45 = vmax(VI{b.x, 4}, VI{b.y, 5});
    VI m67 = vmax(VI{b.z, 6}, VI{b.w, 7});
    VI m03 = vmax(m01, m23);
    VI m47 = vmax(m45, m67);
    const int idx = vmax(m03, m47).i;

    // ---- copy the selected 512-float chunk: 128 float4, 4 per lane ----
    const float4* __restrict__ src = reinterpret_cast<const float4*>(inputs)
        + row * 1024 + idx * 128;
    float4* __restrict__ dst = reinterpret_cast<float4*>(out) + row * 128;

    float4 t0 = __ldcg(src + lane);
    float4 t1 = __ldcg(src + lane + 32);
    float4 t2 = __ldcg(src + lane + 64);
    float4 t3 = __ldcg(src + lane + 96);

    dst[lane]      = t0;
    dst[lane + 32] = t1;
    dst[lane + 64] = t2;
    dst[lane + 96] = t3;
}

extern "C" void kernel_launch(void* const* d_in, const int* in_sizes, int n_in,
                              void* d_out, int out_size) {
    const float* inputs  = (const float*)d_in[0];
    const float* routing = (const float*)d_in[1];
    float* out = (float*)d_out;

    const int B = in_sizes[1] / 8;   // 16384
    const int blocks = B / 8;        // 2048 (8 warps per CTA, 1 row per warp)

    dense_routing_mask_kernel<<<blocks, 256>>>(inputs, routing, out);
}

// round 8
// speedup vs baseline: 1.1815x; 1.0246x over previous
#include <cuda_runtime.h>
#include <cstdint>

// DenseRoutingMaskLayer: per-row argmax over 8 routing logits selects a
// contiguous 512-float chunk of the 4096-wide input row.
//   inputs:          [B=16384, D=4096] f32   (d_in[0])
//   routing_inputs:  [B=16384, R=8]    f32   (d_in[1])
//   out:             [B=16384, W=512]  f32
//
// Round 8: R7 (best, ties R1 at 10.66us) with ONE change: streaming stores.
//  - __stcs on output: evict-first, so the 32MB write stream stops churning
//    L2 and the 32MB hot read set (same rows every graph replay) can stay
//    L2-resident. Reads keep __ldcg (L2-cached, L1-bypass).
//  - everything else identical to R7: 1 row/warp, broadcast float4 routing
//    loads, branchless depth-3 argmax tree (strict '>' keeps lower index ==
//    jnp.argmax first-occurrence ties), 4 loads batched before 4 stores.

struct VI { float v; int i; };

__device__ __forceinline__ VI vmax(VI a, VI b) {
    // b has the higher index; keep a on ties -> first occurrence wins
    VI r;
    r.v = (b.v > a.v) ? b.v : a.v;
    r.i = (b.v > a.v) ? b.i : a.i;
    return r;
}

__global__ __launch_bounds__(256, 8)
void dense_routing_mask_kernel(const float* __restrict__ inputs,
                               const float* __restrict__ routing,
                               float* __restrict__ out) {
    const int warp = threadIdx.x >> 5;
    const int lane = threadIdx.x & 31;
    const int row  = blockIdx.x * 8 + warp;

    // ---- argmax: all lanes load the same 8 logits (broadcast) ----
    const float4* r4 = reinterpret_cast<const float4*>(routing) + row * 2;
    const float4 a = __ldg(r4);
    const float4 b = __ldg(r4 + 1);

    VI m01 = vmax(VI{a.x, 0}, VI{a.y, 1});
    VI m23 = vmax(VI{a.z, 2}, VI{a.w, 3});
    VI m45 = vmax(VI{b.x, 4}, VI{b.y, 5});
    VI m67 = vmax(VI{b.z, 6}, VI{b.w, 7});
    VI m03 = vmax(m01, m23);
    VI m47 = vmax(m45, m67);
    const int idx = vmax(m03, m47).i;

    // ---- copy the selected 512-float chunk: 128 float4, 4 per lane ----
    const float4* __restrict__ src = reinterpret_cast<const float4*>(inputs)
        + row * 1024 + idx * 128;
    float4* __restrict__ dst = reinterpret_cast<float4*>(out) + row * 128;

    float4 t0 = __ldcg(src + lane);
    float4 t1 = __ldcg(src + lane + 32);
    float4 t2 = __ldcg(src + lane + 64);
    float4 t3 = __ldcg(src + lane + 96);

    __stcs(dst + lane,      t0);
    __stcs(dst + lane + 32, t1);
    __stcs(dst + lane + 64, t2);
    __stcs(dst + lane + 96, t3);
}

extern "C" void kernel_launch(void* const* d_in, const int* in_sizes, int n_in,
                              void* d_out, int out_size) {
    const float* inputs  = (const float*)d_in[0];
    const float* routing = (const float*)d_in[1];
    float* out = (float*)d_out;

    const int B = in_sizes[1] / 8;   // 16384
    const int blocks = B / 8;        // 2048 (8 warps per CTA, 1 row per warp)

    dense_routing_mask_kernel<<<blocks, 256>>>(inputs, routing, out);
}